// round 15
// baseline (speedup 1.0000x reference)
#include <cuda_runtime.h>
#include <cuda_fp16.h>
#include <cstdint>
#include <math.h>

#define NPTS  16384
#define HDIM  256
#define G     128
#define NCELL (G*G)
#define KNN   6

#define KREAL 384            // GEMM K (fp16 single-pass)

#define FR_CTAS 64

// ---------------- scratch ----------------
__device__ unsigned g_bbox[4] = {0xFFFFFFFFu, 0u, 0xFFFFFFFFu, 0u};
__device__ int      g_counts[NCELL];
__device__ int      g_starts[NCELL];
__device__ int      g_cursor[NCELL];
__device__ int      g_cellof[NPTS];
__device__ int      g_bsum[FR_CTAS];
__device__ float2   g_pts[NPTS];
__device__ int      g_idx[NPTS];
__device__ float    g_mean[NPTS];
__device__ __half   g_A2[(size_t)NPTS * KREAL];   // fp16 activations
__device__ __half   g_B2[(size_t)HDIM * KREAL];   // fp16 weights, K-major [n][k]
__device__ float    g_bias[HDIM];
// generation-based grid barrier (validated; state returns to cnt=0 after each use)
__device__ unsigned g_bar_cnt = 0;
__device__ unsigned g_bar_gen = 0;

// ---------------- helpers ----------------
__device__ __forceinline__ unsigned fenc(float f) {
    unsigned u = __float_as_uint(f);
    return (u & 0x80000000u) ? ~u : (u | 0x80000000u);
}
__device__ __forceinline__ float fdec(unsigned e) {
    unsigned u = (e & 0x80000000u) ? (e & 0x7FFFFFFFu) : ~e;
    return __uint_as_float(u);
}
__device__ __forceinline__ float silu_f(float x) {
    return __fdividef(x, 1.0f + __expf(-x));
}
__device__ __forceinline__ uint32_t smem_u32(const void* p) {
    uint32_t a;
    asm("{ .reg .u64 t; cvta.to.shared.u64 t, %1; cvt.u32.u64 %0, t; }" : "=r"(a) : "l"(p));
    return a;
}
__device__ __forceinline__ void ldsm_x4(uint32_t* r, uint32_t addr) {
    asm volatile("ldmatrix.sync.aligned.m8n8.x4.shared.b16 {%0,%1,%2,%3}, [%4];"
        : "=r"(r[0]), "=r"(r[1]), "=r"(r[2]), "=r"(r[3]) : "r"(addr));
}
__device__ __forceinline__ void mma_f16(float* d, const uint32_t* a, uint32_t b0, uint32_t b1) {
    asm volatile("mma.sync.aligned.m16n8k16.row.col.f32.f16.f16.f32 "
        "{%0,%1,%2,%3}, {%4,%5,%6,%7}, {%8,%9}, {%0,%1,%2,%3};"
        : "+f"(d[0]), "+f"(d[1]), "+f"(d[2]), "+f"(d[3])
        : "r"(a[0]), "r"(a[1]), "r"(a[2]), "r"(a[3]), "r"(b0), "r"(b1));
}
__device__ __forceinline__ void cp16(uint32_t smem_dst, const void* gsrc) {
    asm volatile("cp.async.cg.shared.global [%0], [%1], 16;" :: "r"(smem_dst), "l"(gsrc) : "memory");
}
#define CP_COMMIT() asm volatile("cp.async.commit_group;" ::: "memory")
#define CP_WAIT(N)  asm volatile("cp.async.wait_group %0;" :: "n"(N) : "memory")

template <int NC>
__device__ __forceinline__ void grid_barrier() {
    __syncthreads();
    if (threadIdx.x == 0) {
        __threadfence();
        unsigned gen = *(volatile unsigned*)&g_bar_gen;   // snapshot BEFORE arrive
        unsigned arrived = atomicAdd(&g_bar_cnt, 1u);
        if (arrived == NC - 1) {
            g_bar_cnt = 0;
            __threadfence();
            atomicAdd(&g_bar_gen, 1u);                    // release
        } else {
            while (*(volatile unsigned*)&g_bar_gen == gen) { __nanosleep(64); }
        }
        __threadfence();
    }
    __syncthreads();
}

struct GridP { float minx, miny, sx, sy, invsx, invsy; };
__device__ __forceinline__ GridP load_grid() {
    GridP gp;
    float minx = fdec(g_bbox[0]), maxx = fdec(g_bbox[1]);
    float miny = fdec(g_bbox[2]), maxy = fdec(g_bbox[3]);
    float rx = maxx - minx, ry = maxy - miny;
    gp.minx = minx; gp.miny = miny;
    gp.sx = rx / (float)G;  gp.sy = ry / (float)G;
    gp.invsx = (rx > 0.f) ? (float)G / rx : 0.f;
    gp.invsy = (ry > 0.f) ? (float)G / ry : 0.f;
    return gp;
}
__device__ __forceinline__ int cell_x(const GridP& gp, float x) {
    int c = (int)((x - gp.minx) * gp.invsx);
    return min(G - 1, max(0, c));
}
__device__ __forceinline__ int cell_y(const GridP& gp, float y) {
    int c = (int)((y - gp.miny) * gp.invsy);
    return min(G - 1, max(0, c));
}

// ---------------- launch 1: front (prep/wprep/bbox -> count -> scan -> prefix -> scatter) ----------------
__global__ __launch_bounds__(256) void k_front(
    const float2* __restrict__ coords,
    const float* __restrict__ W2,  const float* __restrict__ b2,
    const float* __restrict__ Wd2, const float* __restrict__ bd2)
{
    __shared__ int wsum[8];
    int tid = threadIdx.x, lane = tid & 31, warp = tid >> 5;
    int gid = blockIdx.x * 256 + tid;

    g_counts[gid] = 0;
    // wprep: work item = (k8, n), n fastest -> coalesced W2 reads, 16B g_B2 writes.
    // 48 k8-chunks x 256 n = 12288 items.
    if (gid < 12288) {
        int k0 = (gid >> 8) * 8;
        int n  = gid & 255;
        __half h[8];
        #pragma unroll
        for (int kk = 0; kk < 8; kk++) {
            int k = k0 + kk;
            float w = (k < 256) ? W2[k * HDIM + n] : Wd2[(k - 256) * HDIM + n];
            h[kk] = __float2half_rn(w);
        }
        *(uint4*)(g_B2 + (size_t)n * KREAL + k0) = *(uint4*)h;
    }
    if (gid < HDIM) g_bias[gid] = b2[gid] + bd2[gid];
    float2 pt = coords[gid];
    {
        unsigned ex = fenc(pt.x), ey = fenc(pt.y);
        unsigned mnx = ex, mxx = ex, mny = ey, mxy = ey;
        #pragma unroll
        for (int off = 16; off > 0; off >>= 1) {
            mnx = min(mnx, __shfl_xor_sync(0xFFFFFFFFu, mnx, off));
            mxx = max(mxx, __shfl_xor_sync(0xFFFFFFFFu, mxx, off));
            mny = min(mny, __shfl_xor_sync(0xFFFFFFFFu, mny, off));
            mxy = max(mxy, __shfl_xor_sync(0xFFFFFFFFu, mxy, off));
        }
        if (lane == 0) {
            atomicMin(&g_bbox[0], mnx); atomicMax(&g_bbox[1], mxx);
            atomicMin(&g_bbox[2], mny); atomicMax(&g_bbox[3], mxy);
        }
    }
    grid_barrier<FR_CTAS>();

    GridP gp = load_grid();
    {
        int c = cell_y(gp, pt.y) * G + cell_x(gp, pt.x);
        g_cellof[gid] = c;
        atomicAdd(&g_counts[c], 1);
    }
    grid_barrier<FR_CTAS>();

    {
        int v = g_counts[gid];
        int inc = v;
        #pragma unroll
        for (int off = 1; off < 32; off <<= 1) {
            int n = __shfl_up_sync(0xFFFFFFFFu, inc, off);
            if (lane >= off) inc += n;
        }
        if (lane == 31) wsum[warp] = inc;
        __syncthreads();
        if (tid < 8) {
            int w = wsum[tid];
            #pragma unroll
            for (int off = 1; off < 8; off <<= 1) {
                int n = __shfl_up_sync(0xFFu, w, off);
                if (tid >= off) w += n;
            }
            wsum[tid] = w;
        }
        __syncthreads();
        int ex = inc - v + ((warp > 0) ? wsum[warp - 1] : 0);
        g_starts[gid] = ex;
        if (tid == 255) g_bsum[blockIdx.x] = ex + v;
    }
    grid_barrier<FR_CTAS>();

    {
        int pre = 0;
        #pragma unroll
        for (int b = 0; b < FR_CTAS; b++) pre += (b < (int)blockIdx.x) ? g_bsum[b] : 0;
        int st = g_starts[gid] + pre;
        g_starts[gid] = st;
        g_cursor[gid] = st;
    }
    grid_barrier<FR_CTAS>();

    {
        int c = g_cellof[gid];
        int pos = atomicAdd(&g_cursor[c], 1);
        g_pts[pos] = pt;
        g_idx[pos] = gid;
    }
}

// ---------------- launch 2: knn ----------------
__global__ void k_knn() {
    int i = blockIdx.x * blockDim.x + threadIdx.x;
    if (i >= NPTS) return;
    GridP gp = load_grid();
    float2 q = g_pts[i];
    int cx = cell_x(gp, q.x), cy = cell_y(gp, q.y);

    float best[KNN + 1];
    #pragma unroll
    for (int t = 0; t <= KNN; t++) best[t] = 3.4e38f;

    auto scan_cell = [&](int xx, int yy) {
        int c = yy * G + xx;
        int s0 = g_starts[c];
        int e0 = s0 + g_counts[c];
        for (int j = s0; j < e0; j++) {
            float2 p = g_pts[j];
            float dx = q.x - p.x;
            float dy = q.y - p.y;
            float d2 = fmaf(dx, dx, dy * dy);
            if (d2 < best[KNN]) {
                best[KNN] = d2;
                #pragma unroll
                for (int t = KNN; t > 0; t--) {
                    if (best[t] < best[t - 1]) {
                        float tm = best[t - 1]; best[t - 1] = best[t]; best[t] = tm;
                    }
                }
            }
        }
    };

    int r = 0;
    while (true) {
        int xlo = cx - r, xhi = cx + r, ylo = cy - r, yhi = cy + r;
        if (r == 0) {
            scan_cell(cx, cy);
        } else {
            int xa = max(xlo, 0), xb = min(xhi, G - 1);
            if (ylo >= 0)     for (int xx = xa; xx <= xb; xx++) scan_cell(xx, ylo);
            if (yhi <= G - 1) for (int xx = xa; xx <= xb; xx++) scan_cell(xx, yhi);
            int ya = max(ylo + 1, 0), yb = min(yhi - 1, G - 1);
            for (int yy = ya; yy <= yb; yy++) {
                if (xlo >= 0)     scan_cell(xlo, yy);
                if (xhi <= G - 1) scan_cell(xhi, yy);
            }
        }
        bool covered = (xlo <= 0) && (ylo <= 0) && (xhi >= G - 1) && (yhi >= G - 1);
        if (covered) break;
        float bnd = 3.4e38f;
        if (xlo > 0)     bnd = fminf(bnd, q.x - (gp.minx + (float)xlo * gp.sx));
        if (xhi < G - 1) bnd = fminf(bnd, (gp.minx + (float)(xhi + 1) * gp.sx) - q.x);
        if (ylo > 0)     bnd = fminf(bnd, q.y - (gp.miny + (float)ylo * gp.sy));
        if (yhi < G - 1) bnd = fminf(bnd, (gp.miny + (float)(yhi + 1) * gp.sy) - q.y);
        bnd -= 1e-4f;
        if (bnd > 0.f && best[KNN] <= bnd * bnd) break;
        r++;
    }

    float s = 0.f;
    #pragma unroll
    for (int t = 1; t <= KNN; t++) s += sqrtf(fmaxf(best[t], 1e-12f));
    g_mean[g_idx[i]] = s * (1.0f / (float)KNN);
}

// ---------------- launch 3: act (fp16 single plane) ----------------
__global__ void k_act(const float2* __restrict__ coords,
                      const float* __restrict__ W1, const float* __restrict__ b1,
                      const float* __restrict__ Wd1, const float* __restrict__ bd1) {
    int idx = blockIdx.x * blockDim.x + threadIdx.x;
    int m  = idx / (KREAL / 4);
    int kq = (idx % (KREAL / 4)) * 4;
    float o[4];
    if (kq < 256) {
        float2 x  = coords[m];
        float4 w0 = *(const float4*)(W1 + kq);
        float4 w1 = *(const float4*)(W1 + 256 + kq);
        float4 bb = *(const float4*)(b1 + kq);
        o[0] = silu_f(fmaf(x.x, w0.x, fmaf(x.y, w1.x, bb.x)));
        o[1] = silu_f(fmaf(x.x, w0.y, fmaf(x.y, w1.y, bb.y)));
        o[2] = silu_f(fmaf(x.x, w0.z, fmaf(x.y, w1.z, bb.z)));
        o[3] = silu_f(fmaf(x.x, w0.w, fmaf(x.y, w1.w, bb.w)));
    } else {
        int j = kq - 256;
        float md  = g_mean[m];
        float4 w  = *(const float4*)(Wd1 + j);
        float4 bb = *(const float4*)(bd1 + j);
        o[0] = silu_f(fmaf(md, w.x, bb.x));
        o[1] = silu_f(fmaf(md, w.y, bb.y));
        o[2] = silu_f(fmaf(md, w.z, bb.z));
        o[3] = silu_f(fmaf(md, w.w, bb.w));
    }
    __half h[4];
    #pragma unroll
    for (int j = 0; j < 4; j++) h[j] = __float2half_rn(o[j]);
    *(uint2*)(g_A2 + (size_t)m * KREAL + kq) = *(uint2*)h;
}

// ---------------- launch 4: mma.sync GEMM v6.1 (fp16, K=384, issue hoisted before compute) ----------------
// 128x128 CTA tile, 512 threads / 16 warps (4m x 4n), warp tile 32x32, 3-stage cp.async.
#define NCH   12
#define ASTR2 40                 // elem stride (80B/row)
#define STG_B (128 * ASTR2 * 2)  // bytes per stage per array
__global__ __launch_bounds__(512) void k_gemm_mma(float* __restrict__ out) {
    __shared__ __align__(16) __half As[3][128 * ASTR2];
    __shared__ __align__(16) __half Bs[3][128 * ASTR2];
    int tid = threadIdx.x, lane = tid & 31, wid = tid >> 5;
    int wm = (wid & 3) * 32, wn = (wid >> 2) * 32;
    int m0 = blockIdx.y * 128, n0 = blockIdx.x * 128;

    float acc[2][4][4];
    #pragma unroll
    for (int mt = 0; mt < 2; mt++)
        #pragma unroll
        for (int nt = 0; nt < 4; nt++)
            #pragma unroll
            for (int j = 0; j < 4; j++) acc[mt][nt][j] = 0.f;

    uint32_t As_u = smem_u32(As), Bs_u = smem_u32(Bs);
    int a_row = lane & 15, a_kh = lane >> 4;

    // staging: 512 threads, 512 cp16 per array per chunk -> 1 A + 1 B per thread
    auto issue = [&](int c, int st) {
        int kc = c * 32;
        int row = tid >> 2, c8 = (tid & 3) * 8;
        cp16(As_u + st * STG_B + row * 80 + (tid & 3) * 16,
             g_A2 + (size_t)(m0 + row) * KREAL + kc + c8);
        cp16(Bs_u + st * STG_B + row * 80 + (tid & 3) * 16,
             g_B2 + (size_t)(n0 + row) * KREAL + kc + c8);
        CP_COMMIT();
    };

    issue(0, 0);
    issue(1, 1);
    for (int c = 0; c < NCH; c++) {
        int st = c % 3;
        if (c >= NCH - 1) { CP_WAIT(0); } else { CP_WAIT(1); }
        __syncthreads();
        // hoist next-stage issue BEFORE compute: its target stage (c+2)%3 had all
        // its iteration-(c-1) readers complete before this sync -> no race; loads
        // now overlap with the HMMA block below.
        if (c + 2 < NCH) issue(c + 2, (c + 2) % 3);
        uint32_t a_base = As_u + st * STG_B;
        uint32_t b_base = Bs_u + st * STG_B;
        #pragma unroll
        for (int ks = 0; ks < 2; ks++) {
            uint32_t a[2][4], b[2][4];
            #pragma unroll
            for (int mt = 0; mt < 2; mt++)
                ldsm_x4(a[mt], a_base + (wm + mt * 16 + a_row) * 80 + (ks * 16 + a_kh * 8) * 2);
            #pragma unroll
            for (int p = 0; p < 2; p++)
                ldsm_x4(b[p], b_base + (wn + p * 16 + a_row) * 80 + (ks * 16 + a_kh * 8) * 2);
            #pragma unroll
            for (int mt = 0; mt < 2; mt++) {
                mma_f16(acc[mt][0], a[mt], b[0][0], b[0][2]);
                mma_f16(acc[mt][1], a[mt], b[0][1], b[0][3]);
                mma_f16(acc[mt][2], a[mt], b[1][0], b[1][2]);
                mma_f16(acc[mt][3], a[mt], b[1][1], b[1][3]);
            }
        }
    }

    int er = lane >> 2, ec = (lane & 3) * 2;
    #pragma unroll
    for (int mt = 0; mt < 2; mt++) {
        int row0 = m0 + wm + mt * 16 + er;
        #pragma unroll
        for (int nt = 0; nt < 4; nt++) {
            int col = n0 + wn + nt * 8 + ec;
            float2 bv = *(const float2*)(g_bias + col);
            float2 o0 = make_float2(acc[mt][nt][0] + bv.x, acc[mt][nt][1] + bv.y);
            float2 o1 = make_float2(acc[mt][nt][2] + bv.x, acc[mt][nt][3] + bv.y);
            *(float2*)(out + (size_t)row0 * HDIM + col)       = o0;
            *(float2*)(out + (size_t)(row0 + 8) * HDIM + col) = o1;
        }
    }
}

// ---------------- launch ----------------
extern "C" void kernel_launch(void* const* d_in, const int* in_sizes, int n_in,
                              void* d_out, int out_size) {
    const float2* coords = (const float2*)d_in[0];
    const float*  W1  = (const float*)d_in[1];
    const float*  b1  = (const float*)d_in[2];
    const float*  W2  = (const float*)d_in[3];
    const float*  b2  = (const float*)d_in[4];
    const float*  Wd1 = (const float*)d_in[5];
    const float*  bd1 = (const float*)d_in[6];
    const float*  Wd2 = (const float*)d_in[7];
    const float*  bd2 = (const float*)d_in[8];
    float* out = (float*)d_out;

    k_front   <<<FR_CTAS, 256>>>(coords, W2, b2, Wd2, bd2);
    k_knn     <<<NPTS / 128, 128>>>();
    k_act     <<<(NPTS * (KREAL / 4)) / 256, 256>>>(coords, W1, b1, Wd1, bd1);
    k_gemm_mma<<<dim3(2, NPTS / 128), 512>>>(out);
}

// round 16
// speedup vs baseline: 1.0539x; 1.0539x over previous
#include <cuda_runtime.h>
#include <cuda_fp16.h>
#include <cstdint>
#include <math.h>

#define NPTS  16384
#define HDIM  256
#define G     128
#define NCELL (G*G)
#define KNN   6

#define KREAL 384            // GEMM K (fp16 single-pass)

#define FR_CTAS 64

// ---------------- scratch ----------------
__device__ unsigned g_bbox[4] = {0xFFFFFFFFu, 0u, 0xFFFFFFFFu, 0u};
__device__ int      g_counts[NCELL];
__device__ int      g_starts[NCELL];
__device__ int      g_cursor[NCELL];
__device__ int      g_cellof[NPTS];
__device__ int      g_bsum[FR_CTAS];
__device__ float2   g_pts[NPTS];
__device__ int      g_idx[NPTS];
__device__ float    g_mean[NPTS];
__device__ __half   g_A2[(size_t)NPTS * KREAL];   // fp16 activations
__device__ __half   g_B2[(size_t)HDIM * KREAL];   // fp16 weights, K-major [n][k]
__device__ float    g_bias[HDIM];
// generation-based grid barrier (validated; state returns to cnt=0 after each use)
__device__ unsigned g_bar_cnt = 0;
__device__ unsigned g_bar_gen = 0;

// ---------------- helpers ----------------
__device__ __forceinline__ unsigned fenc(float f) {
    unsigned u = __float_as_uint(f);
    return (u & 0x80000000u) ? ~u : (u | 0x80000000u);
}
__device__ __forceinline__ float fdec(unsigned e) {
    unsigned u = (e & 0x80000000u) ? (e & 0x7FFFFFFFu) : ~e;
    return __uint_as_float(u);
}
__device__ __forceinline__ float silu_f(float x) {
    return __fdividef(x, 1.0f + __expf(-x));
}
__device__ __forceinline__ uint32_t smem_u32(const void* p) {
    uint32_t a;
    asm("{ .reg .u64 t; cvta.to.shared.u64 t, %1; cvt.u32.u64 %0, t; }" : "=r"(a) : "l"(p));
    return a;
}
__device__ __forceinline__ void ldsm_x4(uint32_t* r, uint32_t addr) {
    asm volatile("ldmatrix.sync.aligned.m8n8.x4.shared.b16 {%0,%1,%2,%3}, [%4];"
        : "=r"(r[0]), "=r"(r[1]), "=r"(r[2]), "=r"(r[3]) : "r"(addr));
}
__device__ __forceinline__ void mma_f16(float* d, const uint32_t* a, uint32_t b0, uint32_t b1) {
    asm volatile("mma.sync.aligned.m16n8k16.row.col.f32.f16.f16.f32 "
        "{%0,%1,%2,%3}, {%4,%5,%6,%7}, {%8,%9}, {%0,%1,%2,%3};"
        : "+f"(d[0]), "+f"(d[1]), "+f"(d[2]), "+f"(d[3])
        : "r"(a[0]), "r"(a[1]), "r"(a[2]), "r"(a[3]), "r"(b0), "r"(b1));
}
__device__ __forceinline__ void cp16(uint32_t smem_dst, const void* gsrc) {
    asm volatile("cp.async.cg.shared.global [%0], [%1], 16;" :: "r"(smem_dst), "l"(gsrc) : "memory");
}
#define CP_COMMIT() asm volatile("cp.async.commit_group;" ::: "memory")
#define CP_WAIT(N)  asm volatile("cp.async.wait_group %0;" :: "n"(N) : "memory")

template <int NC>
__device__ __forceinline__ void grid_barrier() {
    __syncthreads();
    if (threadIdx.x == 0) {
        __threadfence();
        unsigned gen = *(volatile unsigned*)&g_bar_gen;   // snapshot BEFORE arrive
        unsigned arrived = atomicAdd(&g_bar_cnt, 1u);
        if (arrived == NC - 1) {
            g_bar_cnt = 0;
            __threadfence();
            atomicAdd(&g_bar_gen, 1u);                    // release
        } else {
            while (*(volatile unsigned*)&g_bar_gen == gen) { __nanosleep(64); }
        }
        __threadfence();
    }
    __syncthreads();
}

struct GridP { float minx, miny, sx, sy, invsx, invsy; };
__device__ __forceinline__ GridP load_grid() {
    GridP gp;
    float minx = fdec(g_bbox[0]), maxx = fdec(g_bbox[1]);
    float miny = fdec(g_bbox[2]), maxy = fdec(g_bbox[3]);
    float rx = maxx - minx, ry = maxy - miny;
    gp.minx = minx; gp.miny = miny;
    gp.sx = rx / (float)G;  gp.sy = ry / (float)G;
    gp.invsx = (rx > 0.f) ? (float)G / rx : 0.f;
    gp.invsy = (ry > 0.f) ? (float)G / ry : 0.f;
    return gp;
}
__device__ __forceinline__ int cell_x(const GridP& gp, float x) {
    int c = (int)((x - gp.minx) * gp.invsx);
    return min(G - 1, max(0, c));
}
__device__ __forceinline__ int cell_y(const GridP& gp, float y) {
    int c = (int)((y - gp.miny) * gp.invsy);
    return min(G - 1, max(0, c));
}

// ---------------- launch 1: front (prep/wprep/bbox -> count -> scan -> prefix -> scatter) ----------------
__global__ __launch_bounds__(256) void k_front(
    const float2* __restrict__ coords,
    const float* __restrict__ W2,  const float* __restrict__ b2,
    const float* __restrict__ Wd2, const float* __restrict__ bd2)
{
    __shared__ int wsum[8];
    int tid = threadIdx.x, lane = tid & 31, warp = tid >> 5;
    int gid = blockIdx.x * 256 + tid;

    g_counts[gid] = 0;
    // wprep: work item = (k8, n), n fastest -> coalesced W2 reads, 16B g_B2 writes.
    if (gid < 12288) {
        int k0 = (gid >> 8) * 8;
        int n  = gid & 255;
        __half h[8];
        #pragma unroll
        for (int kk = 0; kk < 8; kk++) {
            int k = k0 + kk;
            float w = (k < 256) ? W2[k * HDIM + n] : Wd2[(k - 256) * HDIM + n];
            h[kk] = __float2half_rn(w);
        }
        *(uint4*)(g_B2 + (size_t)n * KREAL + k0) = *(uint4*)h;
    }
    if (gid < HDIM) g_bias[gid] = b2[gid] + bd2[gid];
    float2 pt = coords[gid];
    {
        unsigned ex = fenc(pt.x), ey = fenc(pt.y);
        unsigned mnx = ex, mxx = ex, mny = ey, mxy = ey;
        #pragma unroll
        for (int off = 16; off > 0; off >>= 1) {
            mnx = min(mnx, __shfl_xor_sync(0xFFFFFFFFu, mnx, off));
            mxx = max(mxx, __shfl_xor_sync(0xFFFFFFFFu, mxx, off));
            mny = min(mny, __shfl_xor_sync(0xFFFFFFFFu, mny, off));
            mxy = max(mxy, __shfl_xor_sync(0xFFFFFFFFu, mxy, off));
        }
        if (lane == 0) {
            atomicMin(&g_bbox[0], mnx); atomicMax(&g_bbox[1], mxx);
            atomicMin(&g_bbox[2], mny); atomicMax(&g_bbox[3], mxy);
        }
    }
    grid_barrier<FR_CTAS>();

    GridP gp = load_grid();
    {
        int c = cell_y(gp, pt.y) * G + cell_x(gp, pt.x);
        g_cellof[gid] = c;
        atomicAdd(&g_counts[c], 1);
    }
    grid_barrier<FR_CTAS>();

    {
        int v = g_counts[gid];
        int inc = v;
        #pragma unroll
        for (int off = 1; off < 32; off <<= 1) {
            int n = __shfl_up_sync(0xFFFFFFFFu, inc, off);
            if (lane >= off) inc += n;
        }
        if (lane == 31) wsum[warp] = inc;
        __syncthreads();
        if (tid < 8) {
            int w = wsum[tid];
            #pragma unroll
            for (int off = 1; off < 8; off <<= 1) {
                int n = __shfl_up_sync(0xFFu, w, off);
                if (tid >= off) w += n;
            }
            wsum[tid] = w;
        }
        __syncthreads();
        int ex = inc - v + ((warp > 0) ? wsum[warp - 1] : 0);
        g_starts[gid] = ex;
        if (tid == 255) g_bsum[blockIdx.x] = ex + v;
    }
    grid_barrier<FR_CTAS>();

    {
        int pre = 0;
        #pragma unroll
        for (int b = 0; b < FR_CTAS; b++) pre += (b < (int)blockIdx.x) ? g_bsum[b] : 0;
        int st = g_starts[gid] + pre;
        g_starts[gid] = st;
        g_cursor[gid] = st;
    }
    grid_barrier<FR_CTAS>();

    {
        int c = g_cellof[gid];
        int pos = atomicAdd(&g_cursor[c], 1);
        g_pts[pos] = pt;
        g_idx[pos] = gid;
    }
}

// ---------------- launch 2: knn ----------------
__global__ void k_knn() {
    int i = blockIdx.x * blockDim.x + threadIdx.x;
    if (i >= NPTS) return;
    GridP gp = load_grid();
    float2 q = g_pts[i];
    int cx = cell_x(gp, q.x), cy = cell_y(gp, q.y);

    float best[KNN + 1];
    #pragma unroll
    for (int t = 0; t <= KNN; t++) best[t] = 3.4e38f;

    auto scan_cell = [&](int xx, int yy) {
        int c = yy * G + xx;
        int s0 = g_starts[c];
        int e0 = s0 + g_counts[c];
        for (int j = s0; j < e0; j++) {
            float2 p = g_pts[j];
            float dx = q.x - p.x;
            float dy = q.y - p.y;
            float d2 = fmaf(dx, dx, dy * dy);
            if (d2 < best[KNN]) {
                best[KNN] = d2;
                #pragma unroll
                for (int t = KNN; t > 0; t--) {
                    if (best[t] < best[t - 1]) {
                        float tm = best[t - 1]; best[t - 1] = best[t]; best[t] = tm;
                    }
                }
            }
        }
    };

    int r = 0;
    while (true) {
        int xlo = cx - r, xhi = cx + r, ylo = cy - r, yhi = cy + r;
        if (r == 0) {
            scan_cell(cx, cy);
        } else {
            int xa = max(xlo, 0), xb = min(xhi, G - 1);
            if (ylo >= 0)     for (int xx = xa; xx <= xb; xx++) scan_cell(xx, ylo);
            if (yhi <= G - 1) for (int xx = xa; xx <= xb; xx++) scan_cell(xx, yhi);
            int ya = max(ylo + 1, 0), yb = min(yhi - 1, G - 1);
            for (int yy = ya; yy <= yb; yy++) {
                if (xlo >= 0)     scan_cell(xlo, yy);
                if (xhi <= G - 1) scan_cell(xhi, yy);
            }
        }
        bool covered = (xlo <= 0) && (ylo <= 0) && (xhi >= G - 1) && (yhi >= G - 1);
        if (covered) break;
        float bnd = 3.4e38f;
        if (xlo > 0)     bnd = fminf(bnd, q.x - (gp.minx + (float)xlo * gp.sx));
        if (xhi < G - 1) bnd = fminf(bnd, (gp.minx + (float)(xhi + 1) * gp.sx) - q.x);
        if (ylo > 0)     bnd = fminf(bnd, q.y - (gp.miny + (float)ylo * gp.sy));
        if (yhi < G - 1) bnd = fminf(bnd, (gp.miny + (float)(yhi + 1) * gp.sy) - q.y);
        bnd -= 1e-4f;
        if (bnd > 0.f && best[KNN] <= bnd * bnd) break;
        r++;
    }

    float s = 0.f;
    #pragma unroll
    for (int t = 1; t <= KNN; t++) s += sqrtf(fmaxf(best[t], 1e-12f));
    g_mean[g_idx[i]] = s * (1.0f / (float)KNN);
}

// ---------------- launch 3: act (fp16 single plane) ----------------
__global__ void k_act(const float2* __restrict__ coords,
                      const float* __restrict__ W1, const float* __restrict__ b1,
                      const float* __restrict__ Wd1, const float* __restrict__ bd1) {
    int idx = blockIdx.x * blockDim.x + threadIdx.x;
    int m  = idx / (KREAL / 4);
    int kq = (idx % (KREAL / 4)) * 4;
    float o[4];
    if (kq < 256) {
        float2 x  = coords[m];
        float4 w0 = *(const float4*)(W1 + kq);
        float4 w1 = *(const float4*)(W1 + 256 + kq);
        float4 bb = *(const float4*)(b1 + kq);
        o[0] = silu_f(fmaf(x.x, w0.x, fmaf(x.y, w1.x, bb.x)));
        o[1] = silu_f(fmaf(x.x, w0.y, fmaf(x.y, w1.y, bb.y)));
        o[2] = silu_f(fmaf(x.x, w0.z, fmaf(x.y, w1.z, bb.z)));
        o[3] = silu_f(fmaf(x.x, w0.w, fmaf(x.y, w1.w, bb.w)));
    } else {
        int j = kq - 256;
        float md  = g_mean[m];
        float4 w  = *(const float4*)(Wd1 + j);
        float4 bb = *(const float4*)(bd1 + j);
        o[0] = silu_f(fmaf(md, w.x, bb.x));
        o[1] = silu_f(fmaf(md, w.y, bb.y));
        o[2] = silu_f(fmaf(md, w.z, bb.z));
        o[3] = silu_f(fmaf(md, w.w, bb.w));
    }
    __half h[4];
    #pragma unroll
    for (int j = 0; j < 4; j++) h[j] = __float2half_rn(o[j]);
    *(uint2*)(g_A2 + (size_t)m * KREAL + kq) = *(uint2*)h;
}

// ---------------- launch 4: mma.sync GEMM v6.2 (fp16, K=384, 2 CTAs/SM -> single wave) ----------------
// 128x128 CTA tile, 512 threads / 16 warps (4m x 4n), warp tile 32x32, 3-stage cp.async.
#define NCH   12
#define ASTR2 40                 // elem stride (80B/row)
#define STG_B (128 * ASTR2 * 2)  // bytes per stage per array
__global__ __launch_bounds__(512, 2) void k_gemm_mma(float* __restrict__ out) {
    __shared__ __align__(16) __half As[3][128 * ASTR2];
    __shared__ __align__(16) __half Bs[3][128 * ASTR2];
    int tid = threadIdx.x, lane = tid & 31, wid = tid >> 5;
    int wm = (wid & 3) * 32, wn = (wid >> 2) * 32;
    int m0 = blockIdx.y * 128, n0 = blockIdx.x * 128;

    float acc[2][4][4];
    #pragma unroll
    for (int mt = 0; mt < 2; mt++)
        #pragma unroll
        for (int nt = 0; nt < 4; nt++)
            #pragma unroll
            for (int j = 0; j < 4; j++) acc[mt][nt][j] = 0.f;

    uint32_t As_u = smem_u32(As), Bs_u = smem_u32(Bs);
    int a_row = lane & 15, a_kh = lane >> 4;

    // staging: 512 threads, 512 cp16 per array per chunk -> 1 A + 1 B per thread
    auto issue = [&](int c, int st) {
        int kc = c * 32;
        int row = tid >> 2, c8 = (tid & 3) * 8;
        cp16(As_u + st * STG_B + row * 80 + (tid & 3) * 16,
             g_A2 + (size_t)(m0 + row) * KREAL + kc + c8);
        cp16(Bs_u + st * STG_B + row * 80 + (tid & 3) * 16,
             g_B2 + (size_t)(n0 + row) * KREAL + kc + c8);
        CP_COMMIT();
    };

    issue(0, 0);
    issue(1, 1);
    for (int c = 0; c < NCH; c++) {
        int st = c % 3;
        if (c >= NCH - 1) { CP_WAIT(0); } else { CP_WAIT(1); }
        __syncthreads();
        // hoisted next-stage issue: stage (c+2)%3's readers finished before this
        // sync -> safe; loads overlap with the HMMA block below.
        if (c + 2 < NCH) issue(c + 2, (c + 2) % 3);
        uint32_t a_base = As_u + st * STG_B;
        uint32_t b_base = Bs_u + st * STG_B;
        #pragma unroll
        for (int ks = 0; ks < 2; ks++) {
            uint32_t a[2][4], b[2][4];
            #pragma unroll
            for (int mt = 0; mt < 2; mt++)
                ldsm_x4(a[mt], a_base + (wm + mt * 16 + a_row) * 80 + (ks * 16 + a_kh * 8) * 2);
            #pragma unroll
            for (int p = 0; p < 2; p++)
                ldsm_x4(b[p], b_base + (wn + p * 16 + a_row) * 80 + (ks * 16 + a_kh * 8) * 2);
            #pragma unroll
            for (int mt = 0; mt < 2; mt++) {
                mma_f16(acc[mt][0], a[mt], b[0][0], b[0][2]);
                mma_f16(acc[mt][1], a[mt], b[0][1], b[0][3]);
                mma_f16(acc[mt][2], a[mt], b[1][0], b[1][2]);
                mma_f16(acc[mt][3], a[mt], b[1][1], b[1][3]);
            }
        }
    }

    int er = lane >> 2, ec = (lane & 3) * 2;
    #pragma unroll
    for (int mt = 0; mt < 2; mt++) {
        int row0 = m0 + wm + mt * 16 + er;
        #pragma unroll
        for (int nt = 0; nt < 4; nt++) {
            int col = n0 + wn + nt * 8 + ec;
            float2 bv = *(const float2*)(g_bias + col);
            float2 o0 = make_float2(acc[mt][nt][0] + bv.x, acc[mt][nt][1] + bv.y);
            float2 o1 = make_float2(acc[mt][nt][2] + bv.x, acc[mt][nt][3] + bv.y);
            *(float2*)(out + (size_t)row0 * HDIM + col)       = o0;
            *(float2*)(out + (size_t)(row0 + 8) * HDIM + col) = o1;
        }
    }
}

// ---------------- launch ----------------
extern "C" void kernel_launch(void* const* d_in, const int* in_sizes, int n_in,
                              void* d_out, int out_size) {
    const float2* coords = (const float2*)d_in[0];
    const float*  W1  = (const float*)d_in[1];
    const float*  b1  = (const float*)d_in[2];
    const float*  W2  = (const float*)d_in[3];
    const float*  b2  = (const float*)d_in[4];
    const float*  Wd1 = (const float*)d_in[5];
    const float*  bd1 = (const float*)d_in[6];
    const float*  Wd2 = (const float*)d_in[7];
    const float*  bd2 = (const float*)d_in[8];
    float* out = (float*)d_out;

    k_front   <<<FR_CTAS, 256>>>(coords, W2, b2, Wd2, bd2);
    k_knn     <<<NPTS / 128, 128>>>();
    k_act     <<<(NPTS * (KREAL / 4)) / 256, 256>>>(coords, W1, b1, Wd1, bd1);
    k_gemm_mma<<<dim3(2, NPTS / 128), 512>>>(out);
}